// round 13
// baseline (speedup 1.0000x reference)
#include <cuda_runtime.h>
#include <cuda_fp16.h>

#define N_CELL  60000
#define N_GENE  4000
#define DIM     128
#define E_EDGES 1500000
#define EPS_BN  1e-5f
#define SCAN_B  ((N_CELL + 1023) / 1024)   // 59

#define PADH 136   // half stride for As/Bs (17*8: ldmatrix-aligned)
#define GEMM_SMEM (2 * 128 * PADH * 2)     // As+Bs fp16
#define NB_OUT ((N_CELL + 127) / 128)      // 469 blocks for out-GEMM
#define NB_Y   ((N_GENE + 127) / 128)      // 32 blocks for y-GEMM

#define CPW 8      // cells per warp in k_aggbn

// ---------------- scratch (static __device__, zero-initialized at load) ------------
// Invariant: every kernel zeroes what it consumed, so each graph replay starts clean.
__device__ int    g_hist[N_CELL];
__device__ int    g_off [N_CELL + 1];
__device__ int    g_rank[E_EDGES];
__device__ int    g_pub [64];              // decoupled-lookback: (aggregate+1) or 0
__device__ int    g_csr [E_EDGES];
__device__ __half g_y   [(size_t)N_GENE * DIM];   // fp16(x_gene @ Wl)
__device__ float  g_colsum[DIM];
__device__ float  g_colsq [DIM];

// ---------------- 1: histogram + per-edge rank (atomics do double duty) ------------
__global__ void k_hist_rank(const int4* __restrict__ dst, int4* __restrict__ rank) {
    int i = blockIdx.x * blockDim.x + threadIdx.x;
    if (i < E_EDGES / 4) {
        int4 d = __ldg(&dst[i]);
        int4 r;
        r.x = atomicAdd(&g_hist[d.x], 1);
        r.y = atomicAdd(&g_hist[d.y], 1);
        r.z = atomicAdd(&g_hist[d.z], 1);
        r.w = atomicAdd(&g_hist[d.w], 1);
        rank[i] = r;
    }
}

// ---------------- 2: single-kernel decoupled-lookback scan ----------------
__global__ void k_scanall() {
    __shared__ int wsum[32];
    __shared__ int exc;
    int b = blockIdx.x;
    int t = threadIdx.x, lane = t & 31, wid = t >> 5;
    if (t == 0) exc = 0;
    int i = b * 1024 + t;
    int v = 0;
    if (i < N_CELL) {
        v = g_hist[i];
        g_hist[i] = 0;               // self-clean for next replay (sole reader)
    }
    int x = v;
    #pragma unroll
    for (int o = 1; o < 32; o <<= 1) {
        int y = __shfl_up_sync(0xffffffffu, x, o);
        if (lane >= o) x += y;
    }
    if (lane == 31) wsum[wid] = x;
    __syncthreads();
    if (wid == 0) {
        int w = wsum[lane];
        #pragma unroll
        for (int o = 1; o < 32; o <<= 1) {
            int y = __shfl_up_sync(0xffffffffu, w, o);
            if (lane >= o) w += y;
        }
        wsum[lane] = w;
    }
    __syncthreads();
    int incl = x + (wid ? wsum[wid - 1] : 0);

    if (t == 1023) atomicExch(&g_pub[b], incl + 1);

    if (t < b) {
        int p;
        do { p = atomicAdd(&g_pub[t], 0); } while (p == 0);
        atomicAdd(&exc, p - 1);
    }
    __syncthreads();
    int off = exc;
    if (i < N_CELL) {
        g_off[i + 1] = incl + off;
        if (i == 0) g_off[0] = 0;
    }
}

// ---------------- 3: atomic-free CSR placement ----------------
__global__ void k_place(const int4* __restrict__ src, const int4* __restrict__ dst,
                        const int4* __restrict__ rank) {
    if (blockIdx.x == 0) {
        int t = threadIdx.x;
        if (t < 64) g_pub[t] = 0;
        else if (t < 192) { g_colsum[t - 64] = 0.f; g_colsq[t - 64] = 0.f; }
    }
    int i = blockIdx.x * blockDim.x + threadIdx.x;
    if (i < E_EDGES / 4) {
        int4 s = __ldg(&src[i]);
        int4 d = __ldg(&dst[i]);
        int4 r = __ldg(&rank[i]);
        g_csr[__ldg(&g_off[d.x]) + r.x] = s.x;
        g_csr[__ldg(&g_off[d.y]) + r.y] = s.y;
        g_csr[__ldg(&g_off[d.z]) + r.z] = s.z;
        g_csr[__ldg(&g_off[d.w]) + r.w] = s.w;
    }
}

// ---------------- 4: unified tensor-core GEMM -------------------------------------
__device__ __forceinline__ unsigned su32(const void* p) {
    return (unsigned)__cvta_generic_to_shared(p);
}
__device__ __forceinline__ void ldsm4(unsigned a, unsigned& r0, unsigned& r1,
                                      unsigned& r2, unsigned& r3) {
    asm volatile("ldmatrix.sync.aligned.m8n8.x4.shared.b16 {%0,%1,%2,%3}, [%4];"
                 : "=r"(r0), "=r"(r1), "=r"(r2), "=r"(r3) : "r"(a));
}
__device__ __forceinline__ void ldsm4t(unsigned a, unsigned& r0, unsigned& r1,
                                       unsigned& r2, unsigned& r3) {
    asm volatile("ldmatrix.sync.aligned.m8n8.x4.trans.shared.b16 {%0,%1,%2,%3}, [%4];"
                 : "=r"(r0), "=r"(r1), "=r"(r2), "=r"(r3) : "r"(a));
}
__device__ __forceinline__ void mma16816(float* d, const unsigned* a, const unsigned* b) {
    asm volatile(
        "mma.sync.aligned.m16n8k16.row.col.f32.f16.f16.f32 "
        "{%0,%1,%2,%3}, {%4,%5,%6,%7}, {%8,%9}, {%0,%1,%2,%3};"
        : "+f"(d[0]), "+f"(d[1]), "+f"(d[2]), "+f"(d[3])
        : "r"(a[0]), "r"(a[1]), "r"(a[2]), "r"(a[3]), "r"(b[0]), "r"(b[1]));
}

__global__ __launch_bounds__(256, 2) void k_gemm_both(
    const float* __restrict__ x_cell,
    const float* __restrict__ Wr,
    const float* __restrict__ x_gene,
    const float* __restrict__ Wl,
    float* __restrict__ out)
{
    extern __shared__ char smem[];
    __half* As = (__half*)smem;                // [128][PADH]
    __half* Bs = (__half*)smem + 128 * PADH;   // [128][PADH], stored [k][n]

    int bid = blockIdx.x;
    bool isY = (bid >= NB_OUT);
    const float* A = isY ? x_gene : x_cell;
    const float* B = isY ? Wl : Wr;
    int M  = isY ? N_GENE : N_CELL;
    int m0 = (isY ? bid - NB_OUT : bid) * 128;

    int tid  = threadIdx.x;
    int warp = tid >> 5, lane = tid & 31;
    int wm = warp & 3, wn = warp >> 2;   // 4 x 2 warp grid; warp tile 32m x 64n

    #pragma unroll
    for (int it = 0; it < 16; it++) {
        int idx = tid + it * 256;
        int row = idx >> 5, q = idx & 31;
        float4 v = {0.f, 0.f, 0.f, 0.f};
        int gm = m0 + row;
        if (gm < M) v = *(const float4*)&A[(size_t)gm * DIM + q * 4];
        *(__half2*)&As[row * PADH + q * 4]     = __floats2half2_rn(v.x, v.y);
        *(__half2*)&As[row * PADH + q * 4 + 2] = __floats2half2_rn(v.z, v.w);
    }
    #pragma unroll
    for (int it = 0; it < 16; it++) {
        int idx = tid + it * 256;
        int k = idx >> 5, n4 = idx & 31;
        float4 v = *(const float4*)&B[(size_t)k * DIM + n4 * 4];
        *(__half2*)&Bs[k * PADH + n4 * 4]     = __floats2half2_rn(v.x, v.y);
        *(__half2*)&Bs[k * PADH + n4 * 4 + 2] = __floats2half2_rn(v.z, v.w);
    }
    __syncthreads();

    float acc[2][8][4];
    #pragma unroll
    for (int tm = 0; tm < 2; tm++)
        #pragma unroll
        for (int tn = 0; tn < 8; tn++)
            #pragma unroll
            for (int j = 0; j < 4; j++) acc[tm][tn][j] = 0.f;

    #pragma unroll
    for (int ks = 0; ks < 8; ks++) {
        unsigned a[2][4], b[8][2];
        #pragma unroll
        for (int tm = 0; tm < 2; tm++) {
            unsigned addr = su32(&As[(wm * 32 + tm * 16 + (lane & 15)) * PADH
                                     + ks * 16 + (lane >> 4) * 8]);
            ldsm4(addr, a[tm][0], a[tm][1], a[tm][2], a[tm][3]);
        }
        #pragma unroll
        for (int tp = 0; tp < 4; tp++) {
            unsigned addr = su32(&Bs[(ks * 16 + (lane & 15)) * PADH
                                     + wn * 64 + tp * 16 + (lane >> 4) * 8]);
            ldsm4t(addr, b[tp * 2][0], b[tp * 2][1], b[tp * 2 + 1][0], b[tp * 2 + 1][1]);
        }
        #pragma unroll
        for (int tm = 0; tm < 2; tm++)
            #pragma unroll
            for (int tn = 0; tn < 8; tn++)
                mma16816(acc[tm][tn], a[tm], b[tn]);
    }

    if (!isY) {
        #pragma unroll
        for (int tm = 0; tm < 2; tm++) {
            int r0 = m0 + wm * 32 + tm * 16 + (lane >> 2);
            #pragma unroll
            for (int tn = 0; tn < 8; tn++) {
                int c = wn * 64 + tn * 8 + (lane & 3) * 2;
                if (r0 < N_CELL)
                    *(float2*)&out[(size_t)r0 * DIM + c] =
                        make_float2(acc[tm][tn][0], acc[tm][tn][1]);
                if (r0 + 8 < N_CELL)
                    *(float2*)&out[(size_t)(r0 + 8) * DIM + c] =
                        make_float2(acc[tm][tn][2], acc[tm][tn][3]);
            }
        }
    } else {
        #pragma unroll
        for (int tm = 0; tm < 2; tm++) {
            int r0 = m0 + wm * 32 + tm * 16 + (lane >> 2);
            #pragma unroll
            for (int tn = 0; tn < 8; tn++) {
                int c = wn * 64 + tn * 8 + (lane & 3) * 2;
                if (r0 < N_GENE)
                    *(__half2*)&g_y[(size_t)r0 * DIM + c] =
                        __floats2half2_rn(acc[tm][tn][0], acc[tm][tn][1]);
                if (r0 + 8 < N_GENE)
                    *(__half2*)&g_y[(size_t)(r0 + 8) * DIM + c] =
                        __floats2half2_rn(acc[tm][tn][2], acc[tm][tn][3]);
            }
        }
    }
}

// ---------------- 5: gather-mean + add into out + BN stats (8-deep MLP) ------------
__global__ __launch_bounds__(256) void k_aggbn(float* __restrict__ out) {
    __shared__ float red[2][8][DIM];
    int tid  = threadIdx.x;
    int warp = tid >> 5, lane = tid & 31;
    const uint2* yv = (const uint2*)g_y;   // 4 halves per lane per gene row

    float s[4] = {0.f, 0.f, 0.f, 0.f};
    float q[4] = {0.f, 0.f, 0.f, 0.f};
    int cell0 = (blockIdx.x * 8 + warp) * CPW;

    int esN = 0, eeN = 0;
    if (cell0 < N_CELL) { esN = g_off[cell0]; eeN = g_off[cell0 + 1]; }

    for (int ci = 0; ci < CPW; ci++) {
        int gm = cell0 + ci;
        if (gm >= N_CELL) break;
        int es = esN, ee = eeN;
        if (gm + 1 < N_CELL) { esN = eeN; eeN = g_off[gm + 2]; }  // prefetch next

        float ax0=0.f, ax1=0.f, ax2=0.f, ax3=0.f;
        float bx0=0.f, bx1=0.f, bx2=0.f, bx3=0.f;
        float cx0=0.f, cx1=0.f, cx2=0.f, cx3=0.f;
        float dx0=0.f, dx1=0.f, dx2=0.f, dx3=0.f;
        int j = es;
        // 8-deep: 8 index loads, then 8 row loads in flight, then convert+accumulate
        for (; j + 7 < ee; j += 8) {
            int g0 = __ldg(&g_csr[j]);
            int g1 = __ldg(&g_csr[j + 1]);
            int g2 = __ldg(&g_csr[j + 2]);
            int g3 = __ldg(&g_csr[j + 3]);
            int g4 = __ldg(&g_csr[j + 4]);
            int g5 = __ldg(&g_csr[j + 5]);
            int g6 = __ldg(&g_csr[j + 6]);
            int g7 = __ldg(&g_csr[j + 7]);
            uint2 u0 = __ldg(&yv[(size_t)g0 * 32 + lane]);
            uint2 u1 = __ldg(&yv[(size_t)g1 * 32 + lane]);
            uint2 u2 = __ldg(&yv[(size_t)g2 * 32 + lane]);
            uint2 u3 = __ldg(&yv[(size_t)g3 * 32 + lane]);
            uint2 u4 = __ldg(&yv[(size_t)g4 * 32 + lane]);
            uint2 u5 = __ldg(&yv[(size_t)g5 * 32 + lane]);
            uint2 u6 = __ldg(&yv[(size_t)g6 * 32 + lane]);
            uint2 u7 = __ldg(&yv[(size_t)g7 * 32 + lane]);
            float2 p, r;
            p = __half22float2(*(__half2*)&u0.x); r = __half22float2(*(__half2*)&u0.y);
            ax0 += p.x; ax1 += p.y; ax2 += r.x; ax3 += r.y;
            p = __half22float2(*(__half2*)&u1.x); r = __half22float2(*(__half2*)&u1.y);
            bx0 += p.x; bx1 += p.y; bx2 += r.x; bx3 += r.y;
            p = __half22float2(*(__half2*)&u2.x); r = __half22float2(*(__half2*)&u2.y);
            cx0 += p.x; cx1 += p.y; cx2 += r.x; cx3 += r.y;
            p = __half22float2(*(__half2*)&u3.x); r = __half22float2(*(__half2*)&u3.y);
            dx0 += p.x; dx1 += p.y; dx2 += r.x; dx3 += r.y;
            p = __half22float2(*(__half2*)&u4.x); r = __half22float2(*(__half2*)&u4.y);
            ax0 += p.x; ax1 += p.y; ax2 += r.x; ax3 += r.y;
            p = __half22float2(*(__half2*)&u5.x); r = __half22float2(*(__half2*)&u5.y);
            bx0 += p.x; bx1 += p.y; bx2 += r.x; bx3 += r.y;
            p = __half22float2(*(__half2*)&u6.x); r = __half22float2(*(__half2*)&u6.y);
            cx0 += p.x; cx1 += p.y; cx2 += r.x; cx3 += r.y;
            p = __half22float2(*(__half2*)&u7.x); r = __half22float2(*(__half2*)&u7.y);
            dx0 += p.x; dx1 += p.y; dx2 += r.x; dx3 += r.y;
        }
        for (; j + 3 < ee; j += 4) {
            int g0 = __ldg(&g_csr[j]);
            int g1 = __ldg(&g_csr[j + 1]);
            int g2 = __ldg(&g_csr[j + 2]);
            int g3 = __ldg(&g_csr[j + 3]);
            uint2 u0 = __ldg(&yv[(size_t)g0 * 32 + lane]);
            uint2 u1 = __ldg(&yv[(size_t)g1 * 32 + lane]);
            uint2 u2 = __ldg(&yv[(size_t)g2 * 32 + lane]);
            uint2 u3 = __ldg(&yv[(size_t)g3 * 32 + lane]);
            float2 p, r;
            p = __half22float2(*(__half2*)&u0.x); r = __half22float2(*(__half2*)&u0.y);
            ax0 += p.x; ax1 += p.y; ax2 += r.x; ax3 += r.y;
            p = __half22float2(*(__half2*)&u1.x); r = __half22float2(*(__half2*)&u1.y);
            bx0 += p.x; bx1 += p.y; bx2 += r.x; bx3 += r.y;
            p = __half22float2(*(__half2*)&u2.x); r = __half22float2(*(__half2*)&u2.y);
            cx0 += p.x; cx1 += p.y; cx2 += r.x; cx3 += r.y;
            p = __half22float2(*(__half2*)&u3.x); r = __half22float2(*(__half2*)&u3.y);
            dx0 += p.x; dx1 += p.y; dx2 += r.x; dx3 += r.y;
        }
        for (; j < ee; j++) {
            int g0 = __ldg(&g_csr[j]);
            uint2 u0 = __ldg(&yv[(size_t)g0 * 32 + lane]);
            float2 p = __half22float2(*(__half2*)&u0.x);
            float2 r = __half22float2(*(__half2*)&u0.y);
            ax0 += p.x; ax1 += p.y; ax2 += r.x; ax3 += r.y;
        }
        float inv = 1.f / (float)max(ee - es, 1);
        float4 v = *(float4*)&out[(size_t)gm * DIM + lane * 4];
        v.x = fmaf(ax0 + bx0 + cx0 + dx0, inv, v.x);
        v.y = fmaf(ax1 + bx1 + cx1 + dx1, inv, v.y);
        v.z = fmaf(ax2 + bx2 + cx2 + dx2, inv, v.z);
        v.w = fmaf(ax3 + bx3 + cx3 + dx3, inv, v.w);
        *(float4*)&out[(size_t)gm * DIM + lane * 4] = v;
        s[0] += v.x; q[0] += v.x * v.x;
        s[1] += v.y; q[1] += v.y * v.y;
        s[2] += v.z; q[2] += v.z * v.z;
        s[3] += v.w; q[3] += v.w * v.w;
    }

    // block-reduce BN partials, one atomic per column per block
    #pragma unroll
    for (int c = 0; c < 4; c++) {
        red[0][warp][lane * 4 + c] = s[c];
        red[1][warp][lane * 4 + c] = q[c];
    }
    __syncthreads();
    if (tid < DIM) {
        float ss = 0.f, qq = 0.f;
        #pragma unroll
        for (int r = 0; r < 8; r++) { ss += red[0][r][tid]; qq += red[1][r][tid]; }
        atomicAdd(&g_colsum[tid], ss);
        atomicAdd(&g_colsq[tid], qq);
    }
}

// ---------------- 6: normalize in place (BN stats finalized inline) ----------------
__global__ void k_norm(float* __restrict__ out) {
    int i = blockIdx.x * blockDim.x + threadIdx.x;   // float4 index
    const int total = N_CELL * DIM / 4;
    if (i < total) {
        int c = (i & 31) * 4;
        const float invN = 1.f / (float)N_CELL;
        float mu0 = g_colsum[c + 0] * invN, mu1 = g_colsum[c + 1] * invN;
        float mu2 = g_colsum[c + 2] * invN, mu3 = g_colsum[c + 3] * invN;
        float rs0 = rsqrtf(g_colsq[c + 0] * invN - mu0 * mu0 + EPS_BN);
        float rs1 = rsqrtf(g_colsq[c + 1] * invN - mu1 * mu1 + EPS_BN);
        float rs2 = rsqrtf(g_colsq[c + 2] * invN - mu2 * mu2 + EPS_BN);
        float rs3 = rsqrtf(g_colsq[c + 3] * invN - mu3 * mu3 + EPS_BN);
        float4 v = ((float4*)out)[i];
        v.x = (v.x - mu0) * rs0;
        v.y = (v.y - mu1) * rs1;
        v.z = (v.z - mu2) * rs2;
        v.w = (v.w - mu3) * rs3;
        ((float4*)out)[i] = v;
    }
}

// ---------------- launch (two-stream fork/join inside graph capture) ----------------
extern "C" void kernel_launch(void* const* d_in, const int* in_sizes, int n_in,
                              void* d_out, int out_size) {
    const float* x_cell = (const float*)d_in[0];
    const float* x_gene = (const float*)d_in[1];
    const float* Wl_gc  = (const float*)d_in[2];
    const float* Wr_gc  = (const float*)d_in[4];
    const int* gc_src = (const int*)d_in[8];
    const int* gc_dst = (const int*)d_in[9];
    float* out = (float*)d_out;

    const float* Wl = Wl_gc + DIM * DIM;   // layer L-1 = 1
    const float* Wr = Wr_gc + DIM * DIM;

    static cudaStream_t sA = nullptr, sB = nullptr;
    static cudaEvent_t  e0 = nullptr, eB = nullptr, eA = nullptr;
    if (!sA) {
        cudaStreamCreateWithFlags(&sA, cudaStreamNonBlocking);
        cudaStreamCreateWithFlags(&sB, cudaStreamNonBlocking);
        cudaEventCreateWithFlags(&e0, cudaEventDisableTiming);
        cudaEventCreateWithFlags(&eB, cudaEventDisableTiming);
        cudaEventCreateWithFlags(&eA, cudaEventDisableTiming);
        cudaFuncSetAttribute(k_gemm_both,
                             cudaFuncAttributeMaxDynamicSharedMemorySize, GEMM_SMEM);
    }

    int* g_rank_p; cudaGetSymbolAddress((void**)&g_rank_p, g_rank);

    // fork from the capture-origin (legacy) stream
    cudaEventRecord(e0, (cudaStream_t)0);
    cudaStreamWaitEvent(sA, e0, 0);
    cudaStreamWaitEvent(sB, e0, 0);

    // chain A: CSR build (atomic-free placement; kernels self-clean their inputs)
    k_hist_rank<<<(E_EDGES / 4 + 255) / 256, 256, 0, sA>>>(
        (const int4*)gc_dst, (int4*)g_rank_p);
    k_scanall  <<<SCAN_B, 1024, 0, sA>>>();
    k_place    <<<(E_EDGES / 4 + 255) / 256, 256, 0, sA>>>(
        (const int4*)gc_src, (const int4*)gc_dst, (const int4*)g_rank_p);

    // chain B: both GEMMs fused into one tensor-core kernel
    k_gemm_both<<<NB_OUT + NB_Y, 256, GEMM_SMEM, sB>>>(x_cell, Wr, x_gene, Wl, out);
    cudaEventRecord(eB, sB);

    // join: aggbn needs CSR + stats zeroed (sA), g_y and out (sB)
    cudaStreamWaitEvent(sA, eB, 0);
    k_aggbn<<<(N_CELL + 8 * CPW - 1) / (8 * CPW), 256, 0, sA>>>(out);
    k_norm <<<(N_CELL * DIM / 4 + 255) / 256, 256, 0, sA>>>(out);

    // join back into the capture-origin stream
    cudaEventRecord(eA, sA);
    cudaStreamWaitEvent((cudaStream_t)0, eA, 0);
}